// round 7
// baseline (speedup 1.0000x reference)
#include <cuda_runtime.h>
#include <cuda_bf16.h>
#include <cstdint>
#include <math.h>

#define B_ 4
#define T_ 1024
#define D_ 1024
#define H_ 16
#define HS 64

// ---------------- device scratch (allocation-free rule) ----------------
__device__ __nv_bfloat16 g_xh[B_*T_*D_];
__device__ __nv_bfloat16 g_xl[B_*T_*D_];
__device__ __nv_bfloat16 g_wth[3*H_*HS*D_];   // [m][h][s][c]  K-major
__device__ __nv_bfloat16 g_wtl[3*H_*HS*D_];
__device__ __nv_bfloat16 g_qh[B_*H_*T_*HS];   // pre-scaled by 0.125
__device__ __nv_bfloat16 g_ql[B_*H_*T_*HS];
__device__ __nv_bfloat16 g_kh[B_*H_*T_*HS];
__device__ __nv_bfloat16 g_kl[B_*H_*T_*HS];
__device__ __nv_bfloat16 g_vh[B_*H_*T_*HS];
__device__ __nv_bfloat16 g_vl[B_*H_*T_*HS];
__device__ __nv_bfloat16 g_yh[B_*T_*D_];
__device__ __nv_bfloat16 g_yl[B_*T_*D_];
__device__ __nv_bfloat16 g_woh[D_*D_];
__device__ __nv_bfloat16 g_wol[D_*D_];

// ---------------- helpers ----------------
__device__ __forceinline__ uint32_t smem_u32(const void* p) {
    uint32_t a;
    asm("{ .reg .u64 t; cvta.to.shared.u64 t, %1; cvt.u32.u64 %0, t; }" : "=r"(a) : "l"(p));
    return a;
}
__device__ __forceinline__ void cpasync16(uint32_t dst, const void* src) {
    asm volatile("cp.async.cg.shared.global [%0], [%1], 16;" :: "r"(dst), "l"(src) : "memory");
}
__device__ __forceinline__ void ldmx4(uint32_t* r, uint32_t addr) {
    asm volatile("ldmatrix.sync.aligned.m8n8.x4.shared.b16 {%0,%1,%2,%3}, [%4];"
                 : "=r"(r[0]), "=r"(r[1]), "=r"(r[2]), "=r"(r[3]) : "r"(addr));
}
__device__ __forceinline__ void ldmx4t(uint32_t* r, uint32_t addr) {
    asm volatile("ldmatrix.sync.aligned.m8n8.x4.trans.shared.b16 {%0,%1,%2,%3}, [%4];"
                 : "=r"(r[0]), "=r"(r[1]), "=r"(r[2]), "=r"(r[3]) : "r"(addr));
}
__device__ __forceinline__ void mma16816(float* d, const uint32_t* a, uint32_t b0, uint32_t b1) {
    asm volatile(
        "mma.sync.aligned.m16n8k16.row.col.f32.bf16.bf16.f32 "
        "{%0,%1,%2,%3}, {%4,%5,%6,%7}, {%8,%9}, {%0,%1,%2,%3};"
        : "+f"(d[0]), "+f"(d[1]), "+f"(d[2]), "+f"(d[3])
        : "r"(a[0]), "r"(a[1]), "r"(a[2]), "r"(a[3]), "r"(b0), "r"(b1));
}
__device__ __forceinline__ uint32_t packbf(float lo, float hi) {
    uint32_t d;
    asm("cvt.rn.bf16x2.f32 %0, %1, %2;" : "=r"(d) : "f"(hi), "f"(lo));
    return d;
}
__device__ __forceinline__ void split_pack(float v0, float v1, uint32_t& ph, uint32_t& pl) {
    __nv_bfloat16 h0 = __float2bfloat16(v0), h1 = __float2bfloat16(v1);
    __nv_bfloat162 hp; hp.x = h0; hp.y = h1;
    ph = *(uint32_t*)&hp;
    pl = packbf(v0 - __bfloat162float(h0), v1 - __bfloat162float(h1));
}

// ---------------------------------------------------------------------------
__global__ __launch_bounds__(256) void conv_pair(
    const float* __restrict__ src, __nv_bfloat16* __restrict__ dh,
    __nv_bfloat16* __restrict__ dl, int n)
{
    int i4 = (blockIdx.x * 256 + threadIdx.x) * 4;
    if (i4 >= n) return;
    float4 v = *(const float4*)(src + i4);
    float vv[4] = {v.x, v.y, v.z, v.w};
    __nv_bfloat16 hh[4], ll[4];
#pragma unroll
    for (int j = 0; j < 4; j++) {
        __nv_bfloat16 hi = __float2bfloat16(vv[j]);
        hh[j] = hi;
        ll[j] = __float2bfloat16(vv[j] - __bfloat162float(hi));
    }
    *(uint2*)(dh + i4) = *(uint2*)hh;
    *(uint2*)(dl + i4) = *(uint2*)ll;
}

// ---------------------------------------------------------------------------
__global__ __launch_bounds__(256) void conv_wt(
    const float* __restrict__ Wq, const float* __restrict__ Wk, const float* __restrict__ Wv)
{
    __shared__ float tile[32][33];
    int z = blockIdx.z;
    int m = z >> 4, h = z & 15;
    int c0 = blockIdx.x * 32, s0 = blockIdx.y * 32;
    int tx = threadIdx.x, ty = threadIdx.y;
    const float* W = (m == 0) ? Wq : (m == 1) ? Wk : Wv;
    const float* Wh_ = W + (size_t)h * D_ * HS;
#pragma unroll
    for (int i = 0; i < 4; i++) {
        int c = c0 + ty + i * 8;
        tile[ty + i * 8][tx] = Wh_[(size_t)c * HS + s0 + tx];
    }
    __syncthreads();
#pragma unroll
    for (int i = 0; i < 4; i++) {
        int sl = ty + i * 8;
        int row = z * 64 + s0 + sl;
        float v = tile[tx][sl];
        __nv_bfloat16 hi = __float2bfloat16(v);
        g_wth[(size_t)row * D_ + c0 + tx] = hi;
        g_wtl[(size_t)row * D_ + c0 + tx] = __float2bfloat16(v - __bfloat162float(hi));
    }
}

// ---------------------------------------------------------------------------
// bf16x3 GEMM via mma.sync; pass-major MMA ordering (acc dep spacing 16).
// ---------------------------------------------------------------------------
#define STAGE_B 40960
#define GEMM_SMEM (2 * STAGE_B)
template <int MODE>
__global__ __launch_bounds__(256, 2) void gemm_bf16x3(
    const __nv_bfloat16* __restrict__ Ah, const __nv_bfloat16* __restrict__ Al,
    const __nv_bfloat16* __restrict__ Bh, const __nv_bfloat16* __restrict__ Bl,
    const float* __restrict__ bias, float* __restrict__ out)
{
    extern __shared__ char smc[];
    const uint32_t sb = smem_u32(smc);
    const int tid = threadIdx.x;
    const int wid = tid >> 5, lane = tid & 31;
    const int wm = wid >> 2, wn = wid & 3;
    const int r0 = blockIdx.x * 128;
    const int brow0 = blockIdx.y * 128;

    const int ldrow = tid >> 2, ldseg = tid & 3;
    const uint32_t dst0 = (uint32_t)(ldrow * 80 + ldseg * 16);
    const size_t gao = (size_t)(r0 + ldrow) * D_ + ldseg * 8;
    const size_t gbo = (size_t)(brow0 + ldrow) * D_ + ldseg * 8;

#define LOAD_CHUNK(c, st) do {                                                  \
    uint32_t _b = sb + (st) * STAGE_B;                                          \
    int _kc = (c) * 32;                                                         \
    _Pragma("unroll")                                                           \
    for (int it = 0; it < 2; ++it) {                                            \
        uint32_t d = _b + dst0 + it * (64 * 80);                                \
        size_t ga = gao + _kc + (size_t)it * 64 * D_;                           \
        size_t gb = gbo + _kc + (size_t)it * 64 * D_;                           \
        cpasync16(d,              Ah + ga);                                     \
        cpasync16(d + 10240,      Al + ga);                                     \
        cpasync16(d + 20480,      Bh + gb);                                     \
        cpasync16(d + 30720,      Bl + gb);                                     \
    }                                                                           \
    asm volatile("cp.async.commit_group;" ::: "memory");                        \
} while (0)

    float acc[4][4][4] = {};
    const uint32_t lmA = (uint32_t)((wm * 64 + (lane & 15)) * 80 + (lane >> 4) * 16);
    const uint32_t lmB = (uint32_t)((wn * 32 + (lane & 15)) * 80 + (lane >> 4) * 16);

    LOAD_CHUNK(0, 0);
    LOAD_CHUNK(1, 1);

    for (int c = 0; c < 32; ++c) {
        asm volatile("cp.async.wait_group 1;" ::: "memory");
        __syncthreads();
        uint32_t base = sb + (c & 1) * STAGE_B;
#pragma unroll
        for (int kk = 0; kk < 2; ++kk) {
            uint32_t ko = (uint32_t)(kk * 32);
            uint32_t ah[4][4], al[4][4], bh[2][4], bl[2][4];
#pragma unroll
            for (int mt = 0; mt < 4; ++mt) {
                uint32_t a = base + lmA + mt * (16 * 80) + ko;
                ldmx4(ah[mt], a);
                ldmx4(al[mt], a + 10240);
            }
#pragma unroll
            for (int g = 0; g < 2; ++g) {
                uint32_t a = base + 20480 + lmB + g * (16 * 80) + ko;
                ldmx4(bh[g], a);
                ldmx4(bl[g], a + 10240);
            }
            // pass-major: same-acc MMAs 16 apart
#pragma unroll
            for (int p = 0; p < 3; ++p)
#pragma unroll
                for (int mt = 0; mt < 4; ++mt)
#pragma unroll
                    for (int nt = 0; nt < 4; ++nt) {
                        int g = nt >> 1, od = nt & 1;
                        const uint32_t* Af = (p == 2) ? al[mt] : ah[mt];
                        uint32_t b0 = (p == 1) ? bl[g][od]     : bh[g][od];
                        uint32_t b1 = (p == 1) ? bl[g][2 + od] : bh[g][2 + od];
                        mma16816(acc[mt][nt], Af, b0, b1);
                    }
        }
        __syncthreads();
        if (c + 2 < 32) LOAD_CHUNK(c + 2, c & 1);
        else asm volatile("cp.async.commit_group;" ::: "memory");
    }

    const int erow = lane >> 2, ecol = (lane & 3) * 2;
#pragma unroll
    for (int mt = 0; mt < 4; ++mt) {
#pragma unroll
        for (int nt = 0; nt < 4; ++nt) {
            int gcol = brow0 + wn * 32 + nt * 8 + ecol;
            int grow = r0 + wm * 64 + mt * 16 + erow;
            if (MODE == 0) {
                int m = gcol >> 10, rem = gcol & 1023;
                int h = rem >> 6, s = rem & 63;
                __nv_bfloat16* dh = (m == 0) ? g_qh : (m == 1) ? g_kh : g_vh;
                __nv_bfloat16* dl = (m == 0) ? g_ql : (m == 1) ? g_kl : g_vl;
                float sc = (m == 0) ? 0.125f : 1.0f;
#pragma unroll
                for (int half = 0; half < 2; ++half) {
                    int r = grow + half * 8;
                    int b = r >> 10, t = r & 1023;
                    size_t idx = ((size_t)(b * H_ + h) * T_ + t) * HS + s;
                    uint32_t ph, pl;
                    split_pack(acc[mt][nt][half * 2] * sc, acc[mt][nt][half * 2 + 1] * sc, ph, pl);
                    *(uint32_t*)(dh + idx) = ph;
                    *(uint32_t*)(dl + idx) = pl;
                }
            } else {
                float2 bv = *(const float2*)(bias + gcol);
#pragma unroll
                for (int half = 0; half < 2; ++half) {
                    int r = grow + half * 8;
                    *(float2*)(out + (size_t)r * D_ + gcol) =
                        make_float2(acc[mt][nt][half * 2] + bv.x,
                                    acc[mt][nt][half * 2 + 1] + bv.y);
                }
            }
        }
    }
#undef LOAD_CHUNK
}

// ---------------------------------------------------------------------------
// Tensor-core causal flash attention; pass-major MMA ordering in S and PV.
// ---------------------------------------------------------------------------
#define AT_PITCH 144
#define AT_ARR 9216
#define AT_STAGE 36864
#define AT_SMEM (2 * AT_STAGE)
__global__ __launch_bounds__(256, 2) void attn_mma()
{
    extern __shared__ char smc[];
    const uint32_t sb = smem_u32(smc);
    const int tid = threadIdx.x, wid = tid >> 5, lane = tid & 31;
    const int qt = 7 - blockIdx.x;
    const int h = blockIdx.y, b = blockIdx.z;
    const int bh = b * H_ + h;
    const size_t bhoff = (size_t)bh * T_ * HS;

    const __nv_bfloat16* qh = g_qh + bhoff + (size_t)qt * 128 * HS;
    const __nv_bfloat16* ql = g_ql + bhoff + (size_t)qt * 128 * HS;
    const __nv_bfloat16* kh = g_kh + bhoff;
    const __nv_bfloat16* kl = g_kl + bhoff;
    const __nv_bfloat16* vh = g_vh + bhoff;
    const __nv_bfloat16* vl = g_vl + bhoff;

#pragma unroll
    for (int it = 0; it < 4; ++it) {
        int u = tid + it * 256;
        int row = u >> 3, seg = u & 7;
        uint32_t d = (uint32_t)(row * AT_PITCH + seg * 16);
        *(uint4*)(smc + d)         = *(const uint4*)(qh + row * HS + seg * 8);
        *(uint4*)(smc + 18432 + d) = *(const uint4*)(ql + row * HS + seg * 8);
    }
    __syncthreads();
    uint32_t aqh[4][4], aql[4][4];
    {
        uint32_t qa = sb + (uint32_t)((wid * 16 + (lane & 15)) * AT_PITCH + (lane >> 4) * 16);
#pragma unroll
        for (int kk = 0; kk < 4; ++kk) {
            ldmx4(aqh[kk], qa + kk * 32);
            ldmx4(aql[kk], qa + 18432 + kk * 32);
        }
    }
    __syncthreads();

    const int nkt = 2 * qt + 2;
    const int lrow = tid >> 2, lq = tid & 3;

#define LOADKV(kt, st) do {                                                     \
    uint32_t _d = sb + (st) * AT_STAGE + (uint32_t)(lrow * AT_PITCH + lq * 16);  \
    size_t _so = (size_t)((kt) * 64 + lrow) * HS + lq * 8;                      \
    cpasync16(_d,                 kh + _so); cpasync16(_d + 64,                 kh + _so + 32); \
    cpasync16(_d + AT_ARR,        kl + _so); cpasync16(_d + AT_ARR + 64,        kl + _so + 32); \
    cpasync16(_d + 2 * AT_ARR,    vh + _so); cpasync16(_d + 2 * AT_ARR + 64,    vh + _so + 32); \
    cpasync16(_d + 3 * AT_ARR,    vl + _so); cpasync16(_d + 3 * AT_ARR + 64,    vl + _so + 32); \
    asm volatile("cp.async.commit_group;" ::: "memory");                        \
} while (0)

    float o[8][4] = {};
    float m0 = -INFINITY, m1 = -INFINITY, l0 = 0.f, l1 = 0.f;
    const int r0 = lane >> 2, c0l = (lane & 3) * 2;
    const int qrow0 = qt * 128 + wid * 16 + r0;

    LOADKV(0, 0);
    LOADKV(1, 1);

    for (int kt = 0; kt < nkt; ++kt) {
        asm volatile("cp.async.wait_group 1;" ::: "memory");
        __syncthreads();
        uint32_t kb = sb + (kt & 1) * AT_STAGE;

        // ---- S = Q K^T : g-pair fragments, pass-major (acc spacing 4) ----
        float sa[8][4] = {};
#pragma unroll
        for (int kk = 0; kk < 4; ++kk) {
#pragma unroll
            for (int gp = 0; gp < 2; ++gp) {
                uint32_t bhf[2][4], blf[2][4];
#pragma unroll
                for (int g2 = 0; g2 < 2; ++g2) {
                    int g = gp * 2 + g2;
                    uint32_t a = kb + (uint32_t)((g * 16 + (lane & 15)) * AT_PITCH + kk * 32 + (lane >> 4) * 16);
                    ldmx4(bhf[g2], a);
                    ldmx4(blf[g2], a + AT_ARR);
                }
#pragma unroll
                for (int p = 0; p < 3; ++p)
#pragma unroll
                    for (int g2 = 0; g2 < 2; ++g2)
#pragma unroll
                        for (int od = 0; od < 2; ++od) {
                            int nt = (gp * 2 + g2) * 2 + od;
                            const uint32_t* Af = (p == 2) ? aql[kk] : aqh[kk];
                            uint32_t b0 = (p == 1) ? blf[g2][od]     : bhf[g2][od];
                            uint32_t b1 = (p == 1) ? blf[g2][2 + od] : bhf[g2][2 + od];
                            mma16816(sa[nt], Af, b0, b1);
                        }
            }
        }

        if (kt >= 2 * qt) {
#pragma unroll
            for (int nt = 0; nt < 8; ++nt) {
                int colb = kt * 64 + nt * 8 + c0l;
                if (colb > qrow0)     sa[nt][0] = -INFINITY;
                if (colb + 1 > qrow0) sa[nt][1] = -INFINITY;
                if (colb > qrow0 + 8)     sa[nt][2] = -INFINITY;
                if (colb + 1 > qrow0 + 8) sa[nt][3] = -INFINITY;
            }
        }

        float mx0 = -INFINITY, mx1 = -INFINITY;
#pragma unroll
        for (int nt = 0; nt < 8; ++nt) {
            mx0 = fmaxf(mx0, fmaxf(sa[nt][0], sa[nt][1]));
            mx1 = fmaxf(mx1, fmaxf(sa[nt][2], sa[nt][3]));
        }
        mx0 = fmaxf(mx0, __shfl_xor_sync(0xffffffffu, mx0, 1));
        mx0 = fmaxf(mx0, __shfl_xor_sync(0xffffffffu, mx0, 2));
        mx1 = fmaxf(mx1, __shfl_xor_sync(0xffffffffu, mx1, 1));
        mx1 = fmaxf(mx1, __shfl_xor_sync(0xffffffffu, mx1, 2));
        float mn0 = fmaxf(m0, mx0), mn1 = fmaxf(m1, mx1);
        float cr0 = __expf(m0 - mn0), cr1 = __expf(m1 - mn1);
        m0 = mn0; m1 = mn1;
        float ls0 = 0.f, ls1 = 0.f;
#pragma unroll
        for (int nt = 0; nt < 8; ++nt) {
            sa[nt][0] = __expf(sa[nt][0] - mn0); ls0 += sa[nt][0];
            sa[nt][1] = __expf(sa[nt][1] - mn0); ls0 += sa[nt][1];
            sa[nt][2] = __expf(sa[nt][2] - mn1); ls1 += sa[nt][2];
            sa[nt][3] = __expf(sa[nt][3] - mn1); ls1 += sa[nt][3];
        }
        ls0 += __shfl_xor_sync(0xffffffffu, ls0, 1);
        ls0 += __shfl_xor_sync(0xffffffffu, ls0, 2);
        ls1 += __shfl_xor_sync(0xffffffffu, ls1, 1);
        ls1 += __shfl_xor_sync(0xffffffffu, ls1, 2);
        l0 = l0 * cr0 + ls0;
        l1 = l1 * cr1 + ls1;
#pragma unroll
        for (int nt = 0; nt < 8; ++nt) {
            o[nt][0] *= cr0; o[nt][1] *= cr0;
            o[nt][2] *= cr1; o[nt][3] *= cr1;
        }

        // ---- O += P V : jj-pair fragments, pass-major (acc spacing 4) ----
#pragma unroll
        for (int kk = 0; kk < 4; ++kk) {
            uint32_t ph[4], pl[4];
            split_pack(sa[2 * kk][0],     sa[2 * kk][1],     ph[0], pl[0]);
            split_pack(sa[2 * kk][2],     sa[2 * kk][3],     ph[1], pl[1]);
            split_pack(sa[2 * kk + 1][0], sa[2 * kk + 1][1], ph[2], pl[2]);
            split_pack(sa[2 * kk + 1][2], sa[2 * kk + 1][3], ph[3], pl[3]);
#pragma unroll
            for (int jp = 0; jp < 2; ++jp) {
                uint32_t vhf[2][4], vlf[2][4];
#pragma unroll
                for (int j2 = 0; j2 < 2; ++j2) {
                    int jj = jp * 2 + j2;
                    uint32_t a = kb + 2 * AT_ARR +
                        (uint32_t)((kk * 16 + (lane & 15)) * AT_PITCH + jj * 32 + (lane >> 4) * 16);
                    ldmx4t(vhf[j2], a);
                    ldmx4t(vlf[j2], a + AT_ARR);
                }
#pragma unroll
                for (int p = 0; p < 3; ++p)
#pragma unroll
                    for (int j2 = 0; j2 < 2; ++j2) {
                        int jj = jp * 2 + j2;
                        const uint32_t* Af = (p == 2) ? pl : ph;
                        uint32_t b0 = (p == 1) ? vlf[j2][0] : vhf[j2][0];
                        uint32_t b1 = (p == 1) ? vlf[j2][1] : vhf[j2][1];
                        mma16816(o[jj * 2], Af, b0, b1);
                        uint32_t b2 = (p == 1) ? vlf[j2][2] : vhf[j2][2];
                        uint32_t b3 = (p == 1) ? vlf[j2][3] : vhf[j2][3];
                        mma16816(o[jj * 2 + 1], Af, b2, b3);
                    }
            }
        }
        __syncthreads();
        if (kt + 2 < nkt) LOADKV(kt + 2, kt & 1);
        else asm volatile("cp.async.commit_group;" ::: "memory");
    }

    float inv0 = 1.f / l0, inv1 = 1.f / l1;
#pragma unroll
    for (int nt = 0; nt < 8; ++nt) {
        int col = nt * 8 + c0l;
        size_t i0 = ((size_t)b * T_ + qrow0) * D_ + h * 64 + col;
        size_t i1 = i0 + (size_t)8 * D_;
        uint32_t ph, pl;
        split_pack(o[nt][0] * inv0, o[nt][1] * inv0, ph, pl);
        *(uint32_t*)(g_yh + i0) = ph;
        *(uint32_t*)(g_yl + i0) = pl;
        split_pack(o[nt][2] * inv1, o[nt][3] * inv1, ph, pl);
        *(uint32_t*)(g_yh + i1) = ph;
        *(uint32_t*)(g_yl + i1) = pl;
    }
#undef LOADKV
}

// ---------------------------------------------------------------------------
extern "C" void kernel_launch(void* const* d_in, const int* in_sizes, int n_in,
                              void* d_out, int out_size)
{
    const float* x  = (const float*)d_in[0];
    const float* Wq = (const float*)d_in[1];
    const float* Wk = (const float*)d_in[2];
    const float* Wv = (const float*)d_in[3];
    const float* Wo = (const float*)d_in[4];
    const float* bo = (const float*)d_in[5];
    float* out = (float*)d_out;

    cudaFuncSetAttribute(gemm_bf16x3<0>, cudaFuncAttributeMaxDynamicSharedMemorySize, GEMM_SMEM);
    cudaFuncSetAttribute(gemm_bf16x3<1>, cudaFuncAttributeMaxDynamicSharedMemorySize, GEMM_SMEM);
    cudaFuncSetAttribute(attn_mma, cudaFuncAttributeMaxDynamicSharedMemorySize, AT_SMEM);

    __nv_bfloat16 *xh, *xl, *wth, *wtl, *yh, *yl, *woh, *wol;
    cudaGetSymbolAddress((void**)&xh,  g_xh);
    cudaGetSymbolAddress((void**)&xl,  g_xl);
    cudaGetSymbolAddress((void**)&wth, g_wth);
    cudaGetSymbolAddress((void**)&wtl, g_wtl);
    cudaGetSymbolAddress((void**)&yh,  g_yh);
    cudaGetSymbolAddress((void**)&yl,  g_yl);
    cudaGetSymbolAddress((void**)&woh, g_woh);
    cudaGetSymbolAddress((void**)&wol, g_wol);

    conv_pair<<<4096, 256>>>(x, xh, xl, B_ * T_ * D_);
    conv_wt<<<dim3(D_ / 32, HS / 32, 48), dim3(32, 8)>>>(Wq, Wk, Wv);
    conv_pair<<<1024, 256>>>(Wo, woh, wol, D_ * D_);

    gemm_bf16x3<0><<<dim3(32, 24), 256, GEMM_SMEM>>>(xh, xl, wth, wtl, bo, out);

    attn_mma<<<dim3(8, H_, B_), 256, AT_SMEM>>>();

    gemm_bf16x3<1><<<dim3(32, 8), 256, GEMM_SMEM>>>(yh, yl, woh, wol, bo, out);
}

// round 8
// speedup vs baseline: 1.4645x; 1.4645x over previous
#include <cuda_runtime.h>
#include <cuda_fp16.h>
#include <cstdint>
#include <math.h>

#define B_ 4
#define T_ 1024
#define D_ 1024
#define H_ 16
#define HS 64

// ---------------- device scratch (allocation-free rule) ----------------
__device__ __half g_xh[B_*T_*D_];             // X rounded to fp16 (single)
__device__ __half g_wth[3*H_*HS*D_];          // [m][h][s][c] K-major, hi
__device__ __half g_wtl[3*H_*HS*D_];          // lo
__device__ __half g_qh[B_*H_*T_*HS];          // q fp16 single, pre-scaled 0.125
__device__ __half g_kh[B_*H_*T_*HS];
__device__ __half g_kl[B_*H_*T_*HS];
__device__ __half g_vh[B_*H_*T_*HS];
__device__ __half g_vl[B_*H_*T_*HS];
__device__ __half g_yh[B_*T_*D_];             // Y fp16 single
__device__ __half g_woh[D_*D_];
__device__ __half g_wol[D_*D_];

// ---------------- helpers ----------------
__device__ __forceinline__ uint32_t smem_u32(const void* p) {
    uint32_t a;
    asm("{ .reg .u64 t; cvta.to.shared.u64 t, %1; cvt.u32.u64 %0, t; }" : "=r"(a) : "l"(p));
    return a;
}
__device__ __forceinline__ void cpasync16(uint32_t dst, const void* src) {
    asm volatile("cp.async.cg.shared.global [%0], [%1], 16;" :: "r"(dst), "l"(src) : "memory");
}
__device__ __forceinline__ void ldmx4(uint32_t* r, uint32_t addr) {
    asm volatile("ldmatrix.sync.aligned.m8n8.x4.shared.b16 {%0,%1,%2,%3}, [%4];"
                 : "=r"(r[0]), "=r"(r[1]), "=r"(r[2]), "=r"(r[3]) : "r"(addr));
}
__device__ __forceinline__ void ldmx4t(uint32_t* r, uint32_t addr) {
    asm volatile("ldmatrix.sync.aligned.m8n8.x4.trans.shared.b16 {%0,%1,%2,%3}, [%4];"
                 : "=r"(r[0]), "=r"(r[1]), "=r"(r[2]), "=r"(r[3]) : "r"(addr));
}
__device__ __forceinline__ void mma16816(float* d, const uint32_t* a, uint32_t b0, uint32_t b1) {
    asm volatile(
        "mma.sync.aligned.m16n8k16.row.col.f32.f16.f16.f32 "
        "{%0,%1,%2,%3}, {%4,%5,%6,%7}, {%8,%9}, {%0,%1,%2,%3};"
        : "+f"(d[0]), "+f"(d[1]), "+f"(d[2]), "+f"(d[3])
        : "r"(a[0]), "r"(a[1]), "r"(a[2]), "r"(a[3]), "r"(b0), "r"(b1));
}
__device__ __forceinline__ uint32_t pack_h2(float v0, float v1) {
    __half2 hp = __halves2half2(__float2half_rn(v0), __float2half_rn(v1));
    return *(uint32_t*)&hp;
}
__device__ __forceinline__ void split_pack_h(float v0, float v1, uint32_t& ph, uint32_t& pl) {
    __half h0 = __float2half_rn(v0), h1 = __float2half_rn(v1);
    __half2 hp = __halves2half2(h0, h1);
    ph = *(uint32_t*)&hp;
    __half2 lp = __halves2half2(__float2half_rn(v0 - __half2float(h0)),
                                __float2half_rn(v1 - __half2float(h1)));
    pl = *(uint32_t*)&lp;
}

// ---------------------------------------------------------------------------
// fp32 -> fp16 (single)
// ---------------------------------------------------------------------------
__global__ __launch_bounds__(256) void conv_single(
    const float* __restrict__ src, __half* __restrict__ dh, int n)
{
    int i4 = (blockIdx.x * 256 + threadIdx.x) * 4;
    if (i4 >= n) return;
    float4 v = *(const float4*)(src + i4);
    __half hh[4] = {__float2half_rn(v.x), __float2half_rn(v.y),
                    __float2half_rn(v.z), __float2half_rn(v.w)};
    *(uint2*)(dh + i4) = *(uint2*)hh;
}

// ---------------------------------------------------------------------------
// fp32 -> fp16 hi/lo split
// ---------------------------------------------------------------------------
__global__ __launch_bounds__(256) void conv_pair(
    const float* __restrict__ src, __half* __restrict__ dh,
    __half* __restrict__ dl, int n)
{
    int i4 = (blockIdx.x * 256 + threadIdx.x) * 4;
    if (i4 >= n) return;
    float4 v = *(const float4*)(src + i4);
    float vv[4] = {v.x, v.y, v.z, v.w};
    __half hh[4], ll[4];
#pragma unroll
    for (int j = 0; j < 4; j++) {
        __half hi = __float2half_rn(vv[j]);
        hh[j] = hi;
        ll[j] = __float2half_rn(vv[j] - __half2float(hi));
    }
    *(uint2*)(dh + i4) = *(uint2*)hh;
    *(uint2*)(dl + i4) = *(uint2*)ll;
}

// ---------------------------------------------------------------------------
// Wq/Wk/Wv [H][D][HS] -> Wt[m*16+h][s][c] K-major fp16 hi/lo
// ---------------------------------------------------------------------------
__global__ __launch_bounds__(256) void conv_wt(
    const float* __restrict__ Wq, const float* __restrict__ Wk, const float* __restrict__ Wv)
{
    __shared__ float tile[32][33];
    int z = blockIdx.z;
    int m = z >> 4, h = z & 15;
    int c0 = blockIdx.x * 32, s0 = blockIdx.y * 32;
    int tx = threadIdx.x, ty = threadIdx.y;
    const float* W = (m == 0) ? Wq : (m == 1) ? Wk : Wv;
    const float* Wh_ = W + (size_t)h * D_ * HS;
#pragma unroll
    for (int i = 0; i < 4; i++) {
        int c = c0 + ty + i * 8;
        tile[ty + i * 8][tx] = Wh_[(size_t)c * HS + s0 + tx];
    }
    __syncthreads();
#pragma unroll
    for (int i = 0; i < 4; i++) {
        int sl = ty + i * 8;
        int row = z * 64 + s0 + sl;
        float v = tile[tx][sl];
        __half hi = __float2half_rn(v);
        g_wth[(size_t)row * D_ + c0 + tx] = hi;
        g_wtl[(size_t)row * D_ + c0 + tx] = __float2half_rn(v - __half2float(hi));
    }
}

// ---------------------------------------------------------------------------
// fp16 2-pass GEMM: C = Ah·Bh^T + Ah·Bl^T. A single fp16, B hi/lo.
// MODE 0: QKV scatter (q single scaled, k/v hi/lo). MODE 1: out = C + bias.
// ---------------------------------------------------------------------------
#define STAGE_B 30720   // 3 arrays * 128 rows * 80 B
#define GEMM_SMEM (2 * STAGE_B)
template <int MODE>
__global__ __launch_bounds__(256, 2) void gemm_f16x2(
    const __half* __restrict__ Ah,
    const __half* __restrict__ Bh, const __half* __restrict__ Bl,
    const float* __restrict__ bias, float* __restrict__ out)
{
    extern __shared__ char smc[];
    const uint32_t sb = smem_u32(smc);
    const int tid = threadIdx.x;
    const int wid = tid >> 5, lane = tid & 31;
    const int wm = wid >> 2, wn = wid & 3;
    const int r0 = blockIdx.x * 128;
    const int brow0 = blockIdx.y * 128;

    const int ldrow = tid >> 2, ldseg = tid & 3;
    const uint32_t dst0 = (uint32_t)(ldrow * 80 + ldseg * 16);
    const size_t gao = (size_t)(r0 + ldrow) * D_ + ldseg * 8;
    const size_t gbo = (size_t)(brow0 + ldrow) * D_ + ldseg * 8;

#define LOAD_CHUNK(c, st) do {                                                  \
    uint32_t _b = sb + (st) * STAGE_B;                                          \
    int _kc = (c) * 32;                                                         \
    _Pragma("unroll")                                                           \
    for (int it = 0; it < 2; ++it) {                                            \
        uint32_t d = _b + dst0 + it * (64 * 80);                                \
        size_t ga = gao + _kc + (size_t)it * 64 * D_;                           \
        size_t gb = gbo + _kc + (size_t)it * 64 * D_;                           \
        cpasync16(d,          Ah + ga);                                         \
        cpasync16(d + 10240,  Bh + gb);                                         \
        cpasync16(d + 20480,  Bl + gb);                                         \
    }                                                                           \
    asm volatile("cp.async.commit_group;" ::: "memory");                        \
} while (0)

    float acc[4][4][4] = {};
    const uint32_t lmA = (uint32_t)((wm * 64 + (lane & 15)) * 80 + (lane >> 4) * 16);
    const uint32_t lmB = (uint32_t)((wn * 32 + (lane & 15)) * 80 + (lane >> 4) * 16);

    LOAD_CHUNK(0, 0);
    LOAD_CHUNK(1, 1);

    for (int c = 0; c < 32; ++c) {
        asm volatile("cp.async.wait_group 1;" ::: "memory");
        __syncthreads();
        uint32_t base = sb + (c & 1) * STAGE_B;
#pragma unroll
        for (int kk = 0; kk < 2; ++kk) {
            uint32_t ko = (uint32_t)(kk * 32);
            uint32_t ah[4][4], bh[2][4], bl[2][4];
#pragma unroll
            for (int mt = 0; mt < 4; ++mt)
                ldmx4(ah[mt], base + lmA + mt * (16 * 80) + ko);
#pragma unroll
            for (int g = 0; g < 2; ++g) {
                uint32_t a = base + 10240 + lmB + g * (16 * 80) + ko;
                ldmx4(bh[g], a);
                ldmx4(bl[g], a + 10240);
            }
#pragma unroll
            for (int p = 0; p < 2; ++p)
#pragma unroll
                for (int mt = 0; mt < 4; ++mt)
#pragma unroll
                    for (int nt = 0; nt < 4; ++nt) {
                        int g = nt >> 1, od = nt & 1;
                        uint32_t b0 = (p == 1) ? bl[g][od]     : bh[g][od];
                        uint32_t b1 = (p == 1) ? bl[g][2 + od] : bh[g][2 + od];
                        mma16816(acc[mt][nt], ah[mt], b0, b1);
                    }
        }
        __syncthreads();
        if (c + 2 < 32) LOAD_CHUNK(c + 2, c & 1);
        else asm volatile("cp.async.commit_group;" ::: "memory");
    }

    const int erow = lane >> 2, ecol = (lane & 3) * 2;
#pragma unroll
    for (int mt = 0; mt < 4; ++mt) {
#pragma unroll
        for (int nt = 0; nt < 4; ++nt) {
            int gcol = brow0 + wn * 32 + nt * 8 + ecol;
            int grow = r0 + wm * 64 + mt * 16 + erow;
            if (MODE == 0) {
                int m = gcol >> 10, rem = gcol & 1023;
                int h = rem >> 6, s = rem & 63;
#pragma unroll
                for (int half = 0; half < 2; ++half) {
                    int r = grow + half * 8;
                    int b = r >> 10, t = r & 1023;
                    size_t idx = ((size_t)(b * H_ + h) * T_ + t) * HS + s;
                    float v0 = acc[mt][nt][half * 2], v1 = acc[mt][nt][half * 2 + 1];
                    if (m == 0) {
                        *(uint32_t*)(g_qh + idx) = pack_h2(v0 * 0.125f, v1 * 0.125f);
                    } else {
                        uint32_t ph, pl;
                        split_pack_h(v0, v1, ph, pl);
                        __half* dh = (m == 1) ? g_kh : g_vh;
                        __half* dl = (m == 1) ? g_kl : g_vl;
                        *(uint32_t*)(dh + idx) = ph;
                        *(uint32_t*)(dl + idx) = pl;
                    }
                }
            } else {
                float2 bv = *(const float2*)(bias + gcol);
#pragma unroll
                for (int half = 0; half < 2; ++half) {
                    int r = grow + half * 8;
                    *(float2*)(out + (size_t)r * D_ + gcol) =
                        make_float2(acc[mt][nt][half * 2] + bv.x,
                                    acc[mt][nt][half * 2 + 1] + bv.y);
                }
            }
        }
    }
#undef LOAD_CHUNK
}

// ---------------------------------------------------------------------------
// fp16 tensor-core causal flash attention.
// S = q (single) x K (hi/lo, 2 passes); O += P (single) x V (hi/lo, 2 passes).
// ---------------------------------------------------------------------------
#define AT_PITCH 144
#define AT_ARR 9216
#define AT_STAGE 36864
#define AT_SMEM (2 * AT_STAGE)
__global__ __launch_bounds__(256, 2) void attn_mma()
{
    extern __shared__ char smc[];
    const uint32_t sb = smem_u32(smc);
    const int tid = threadIdx.x, wid = tid >> 5, lane = tid & 31;
    const int qt = 7 - blockIdx.x;
    const int h = blockIdx.y, b = blockIdx.z;
    const int bh = b * H_ + h;
    const size_t bhoff = (size_t)bh * T_ * HS;

    const __half* qp = g_qh + bhoff + (size_t)qt * 128 * HS;
    const __half* kh = g_kh + bhoff;
    const __half* kl = g_kl + bhoff;
    const __half* vh = g_vh + bhoff;
    const __half* vl = g_vl + bhoff;

    // ---- stage Q (single), load fragments ----
#pragma unroll
    for (int it = 0; it < 4; ++it) {
        int u = tid + it * 256;
        int row = u >> 3, seg = u & 7;
        *(uint4*)(smc + row * AT_PITCH + seg * 16) =
            *(const uint4*)(qp + row * HS + seg * 8);
    }
    __syncthreads();
    uint32_t aq[4][4];
    {
        uint32_t qa = sb + (uint32_t)((wid * 16 + (lane & 15)) * AT_PITCH + (lane >> 4) * 16);
#pragma unroll
        for (int kk = 0; kk < 4; ++kk)
            ldmx4(aq[kk], qa + kk * 32);
    }
    __syncthreads();

    const int nkt = 2 * qt + 2;
    const int lrow = tid >> 2, lq = tid & 3;

#define LOADKV(kt, st) do {                                                     \
    uint32_t _d = sb + (st) * AT_STAGE + (uint32_t)(lrow * AT_PITCH + lq * 16);  \
    size_t _so = (size_t)((kt) * 64 + lrow) * HS + lq * 8;                      \
    cpasync16(_d,                 kh + _so); cpasync16(_d + 64,                 kh + _so + 32); \
    cpasync16(_d + AT_ARR,        kl + _so); cpasync16(_d + AT_ARR + 64,        kl + _so + 32); \
    cpasync16(_d + 2 * AT_ARR,    vh + _so); cpasync16(_d + 2 * AT_ARR + 64,    vh + _so + 32); \
    cpasync16(_d + 3 * AT_ARR,    vl + _so); cpasync16(_d + 3 * AT_ARR + 64,    vl + _so + 32); \
    asm volatile("cp.async.commit_group;" ::: "memory");                        \
} while (0)

    float o[8][4] = {};
    float m0 = -INFINITY, m1 = -INFINITY, l0 = 0.f, l1 = 0.f;
    const int r0 = lane >> 2, c0l = (lane & 3) * 2;
    const int qrow0 = qt * 128 + wid * 16 + r0;

    LOADKV(0, 0);
    LOADKV(1, 1);

    for (int kt = 0; kt < nkt; ++kt) {
        asm volatile("cp.async.wait_group 1;" ::: "memory");
        __syncthreads();
        uint32_t kb = sb + (kt & 1) * AT_STAGE;

        // ---- S = q K^T (2 passes) ----
        float sa[8][4] = {};
#pragma unroll
        for (int kk = 0; kk < 4; ++kk) {
#pragma unroll
            for (int gp = 0; gp < 2; ++gp) {
                uint32_t bhf[2][4], blf[2][4];
#pragma unroll
                for (int g2 = 0; g2 < 2; ++g2) {
                    int g = gp * 2 + g2;
                    uint32_t a = kb + (uint32_t)((g * 16 + (lane & 15)) * AT_PITCH + kk * 32 + (lane >> 4) * 16);
                    ldmx4(bhf[g2], a);
                    ldmx4(blf[g2], a + AT_ARR);
                }
#pragma unroll
                for (int p = 0; p < 2; ++p)
#pragma unroll
                    for (int g2 = 0; g2 < 2; ++g2)
#pragma unroll
                        for (int od = 0; od < 2; ++od) {
                            int nt = (gp * 2 + g2) * 2 + od;
                            uint32_t b0 = (p == 1) ? blf[g2][od]     : bhf[g2][od];
                            uint32_t b1 = (p == 1) ? blf[g2][2 + od] : bhf[g2][2 + od];
                            mma16816(sa[nt], aq[kk], b0, b1);
                        }
            }
        }

        if (kt >= 2 * qt) {
#pragma unroll
            for (int nt = 0; nt < 8; ++nt) {
                int colb = kt * 64 + nt * 8 + c0l;
                if (colb > qrow0)     sa[nt][0] = -INFINITY;
                if (colb + 1 > qrow0) sa[nt][1] = -INFINITY;
                if (colb > qrow0 + 8)     sa[nt][2] = -INFINITY;
                if (colb + 1 > qrow0 + 8) sa[nt][3] = -INFINITY;
            }
        }

        float mx0 = -INFINITY, mx1 = -INFINITY;
#pragma unroll
        for (int nt = 0; nt < 8; ++nt) {
            mx0 = fmaxf(mx0, fmaxf(sa[nt][0], sa[nt][1]));
            mx1 = fmaxf(mx1, fmaxf(sa[nt][2], sa[nt][3]));
        }
        mx0 = fmaxf(mx0, __shfl_xor_sync(0xffffffffu, mx0, 1));
        mx0 = fmaxf(mx0, __shfl_xor_sync(0xffffffffu, mx0, 2));
        mx1 = fmaxf(mx1, __shfl_xor_sync(0xffffffffu, mx1, 1));
        mx1 = fmaxf(mx1, __shfl_xor_sync(0xffffffffu, mx1, 2));
        float mn0 = fmaxf(m0, mx0), mn1 = fmaxf(m1, mx1);
        float cr0 = __expf(m0 - mn0), cr1 = __expf(m1 - mn1);
        m0 = mn0; m1 = mn1;
        float ls0 = 0.f, ls1 = 0.f;
#pragma unroll
        for (int nt = 0; nt < 8; ++nt) {
            sa[nt][0] = __expf(sa[nt][0] - mn0); ls0 += sa[nt][0];
            sa[nt][1] = __expf(sa[nt][1] - mn0); ls0 += sa[nt][1];
            sa[nt][2] = __expf(sa[nt][2] - mn1); ls1 += sa[nt][2];
            sa[nt][3] = __expf(sa[nt][3] - mn1); ls1 += sa[nt][3];
        }
        ls0 += __shfl_xor_sync(0xffffffffu, ls0, 1);
        ls0 += __shfl_xor_sync(0xffffffffu, ls0, 2);
        ls1 += __shfl_xor_sync(0xffffffffu, ls1, 1);
        ls1 += __shfl_xor_sync(0xffffffffu, ls1, 2);
        l0 = l0 * cr0 + ls0;
        l1 = l1 * cr1 + ls1;
#pragma unroll
        for (int nt = 0; nt < 8; ++nt) {
            o[nt][0] *= cr0; o[nt][1] *= cr0;
            o[nt][2] *= cr1; o[nt][3] *= cr1;
        }

        // ---- O += P V (P single, V hi/lo: 2 passes) ----
#pragma unroll
        for (int kk = 0; kk < 4; ++kk) {
            uint32_t ph[4];
            ph[0] = pack_h2(sa[2 * kk][0],     sa[2 * kk][1]);
            ph[1] = pack_h2(sa[2 * kk][2],     sa[2 * kk][3]);
            ph[2] = pack_h2(sa[2 * kk + 1][0], sa[2 * kk + 1][1]);
            ph[3] = pack_h2(sa[2 * kk + 1][2], sa[2 * kk + 1][3]);
#pragma unroll
            for (int jp = 0; jp < 2; ++jp) {
                uint32_t vhf[2][4], vlf[2][4];
#pragma unroll
                for (int j2 = 0; j2 < 2; ++j2) {
                    int jj = jp * 2 + j2;
                    uint32_t a = kb + 2 * AT_ARR +
                        (uint32_t)((kk * 16 + (lane & 15)) * AT_PITCH + jj * 32 + (lane >> 4) * 16);
                    ldmx4t(vhf[j2], a);
                    ldmx4t(vlf[j2], a + AT_ARR);
                }
#pragma unroll
                for (int p = 0; p < 2; ++p)
#pragma unroll
                    for (int j2 = 0; j2 < 2; ++j2) {
                        int jj = jp * 2 + j2;
                        uint32_t b0 = (p == 1) ? vlf[j2][0] : vhf[j2][0];
                        uint32_t b1 = (p == 1) ? vlf[j2][1] : vhf[j2][1];
                        mma16816(o[jj * 2], ph, b0, b1);
                        uint32_t b2 = (p == 1) ? vlf[j2][2] : vhf[j2][2];
                        uint32_t b3 = (p == 1) ? vlf[j2][3] : vhf[j2][3];
                        mma16816(o[jj * 2 + 1], ph, b2, b3);
                    }
            }
        }
        __syncthreads();
        if (kt + 2 < nkt) LOADKV(kt + 2, kt & 1);
        else asm volatile("cp.async.commit_group;" ::: "memory");
    }

    float inv0 = 1.f / l0, inv1 = 1.f / l1;
#pragma unroll
    for (int nt = 0; nt < 8; ++nt) {
        int col = nt * 8 + c0l;
        size_t i0 = ((size_t)b * T_ + qrow0) * D_ + h * 64 + col;
        size_t i1 = i0 + (size_t)8 * D_;
        *(uint32_t*)(g_yh + i0) = pack_h2(o[nt][0] * inv0, o[nt][1] * inv0);
        *(uint32_t*)(g_yh + i1) = pack_h2(o[nt][2] * inv1, o[nt][3] * inv1);
    }
#undef LOADKV
}

// ---------------------------------------------------------------------------
extern "C" void kernel_launch(void* const* d_in, const int* in_sizes, int n_in,
                              void* d_out, int out_size)
{
    const float* x  = (const float*)d_in[0];
    const float* Wq = (const float*)d_in[1];
    const float* Wk = (const float*)d_in[2];
    const float* Wv = (const float*)d_in[3];
    const float* Wo = (const float*)d_in[4];
    const float* bo = (const float*)d_in[5];
    float* out = (float*)d_out;

    cudaFuncSetAttribute(gemm_f16x2<0>, cudaFuncAttributeMaxDynamicSharedMemorySize, GEMM_SMEM);
    cudaFuncSetAttribute(gemm_f16x2<1>, cudaFuncAttributeMaxDynamicSharedMemorySize, GEMM_SMEM);
    cudaFuncSetAttribute(attn_mma, cudaFuncAttributeMaxDynamicSharedMemorySize, AT_SMEM);

    __half *xh, *wth, *wtl, *yh, *woh, *wol;
    cudaGetSymbolAddress((void**)&xh,  g_xh);
    cudaGetSymbolAddress((void**)&wth, g_wth);
    cudaGetSymbolAddress((void**)&wtl, g_wtl);
    cudaGetSymbolAddress((void**)&yh,  g_yh);
    cudaGetSymbolAddress((void**)&woh, g_woh);
    cudaGetSymbolAddress((void**)&wol, g_wol);

    conv_single<<<4096, 256>>>(x, xh, B_ * T_ * D_);
    conv_wt<<<dim3(D_ / 32, HS / 32, 48), dim3(32, 8)>>>(Wq, Wk, Wv);
    conv_pair<<<1024, 256>>>(Wo, woh, wol, D_ * D_);

    // QKV: A = X[4096,1024] fp16, B = Wt[3072,1024] hi/lo
    gemm_f16x2<0><<<dim3(32, 24), 256, GEMM_SMEM>>>(xh, wth, wtl, bo, out);

    attn_mma<<<dim3(8, H_, B_), 256, AT_SMEM>>>();

    // O-proj: A = Y[4096,1024] fp16, B = Wo[1024,1024] hi/lo
    gemm_f16x2<1><<<dim3(32, 8), 256, GEMM_SMEM>>>(yh, woh, wol, bo, out);
}

// round 9
// speedup vs baseline: 2.3956x; 1.6358x over previous
#include <cuda_runtime.h>
#include <cuda_fp16.h>
#include <cstdint>
#include <math.h>

#define B_ 4
#define T_ 1024
#define D_ 1024
#define H_ 16
#define HS 64

// ---------------- device scratch (allocation-free rule) ----------------
__device__ __half g_xh[B_*T_*D_];             // X fp16
__device__ __half g_wth[3*H_*HS*D_];          // [m][h][s][c] K-major fp16
__device__ __half g_qh[B_*H_*T_*HS];          // q fp16, pre-scaled 0.125
__device__ __half g_kh[B_*H_*T_*HS];
__device__ __half g_vh[B_*H_*T_*HS];
__device__ __half g_yh[B_*T_*D_];             // Y fp16
__device__ __half g_woh[D_*D_];

// ---------------- helpers ----------------
__device__ __forceinline__ uint32_t smem_u32(const void* p) {
    uint32_t a;
    asm("{ .reg .u64 t; cvta.to.shared.u64 t, %1; cvt.u32.u64 %0, t; }" : "=r"(a) : "l"(p));
    return a;
}
__device__ __forceinline__ void cpasync16(uint32_t dst, const void* src) {
    asm volatile("cp.async.cg.shared.global [%0], [%1], 16;" :: "r"(dst), "l"(src) : "memory");
}
__device__ __forceinline__ void ldmx4(uint32_t* r, uint32_t addr) {
    asm volatile("ldmatrix.sync.aligned.m8n8.x4.shared.b16 {%0,%1,%2,%3}, [%4];"
                 : "=r"(r[0]), "=r"(r[1]), "=r"(r[2]), "=r"(r[3]) : "r"(addr));
}
__device__ __forceinline__ void ldmx4t(uint32_t* r, uint32_t addr) {
    asm volatile("ldmatrix.sync.aligned.m8n8.x4.trans.shared.b16 {%0,%1,%2,%3}, [%4];"
                 : "=r"(r[0]), "=r"(r[1]), "=r"(r[2]), "=r"(r[3]) : "r"(addr));
}
__device__ __forceinline__ void mma16816(float* d, const uint32_t* a, uint32_t b0, uint32_t b1) {
    asm volatile(
        "mma.sync.aligned.m16n8k16.row.col.f32.f16.f16.f32 "
        "{%0,%1,%2,%3}, {%4,%5,%6,%7}, {%8,%9}, {%0,%1,%2,%3};"
        : "+f"(d[0]), "+f"(d[1]), "+f"(d[2]), "+f"(d[3])
        : "r"(a[0]), "r"(a[1]), "r"(a[2]), "r"(a[3]), "r"(b0), "r"(b1));
}
__device__ __forceinline__ uint32_t pack_h2(float v0, float v1) {
    __half2 hp = __halves2half2(__float2half_rn(v0), __float2half_rn(v1));
    return *(uint32_t*)&hp;
}

// ---------------------------------------------------------------------------
// fp32 -> fp16
// ---------------------------------------------------------------------------
__global__ __launch_bounds__(256) void conv_single(
    const float* __restrict__ src, __half* __restrict__ dh, int n)
{
    int i4 = (blockIdx.x * 256 + threadIdx.x) * 4;
    if (i4 >= n) return;
    float4 v = *(const float4*)(src + i4);
    __half hh[4] = {__float2half_rn(v.x), __float2half_rn(v.y),
                    __float2half_rn(v.z), __float2half_rn(v.w)};
    *(uint2*)(dh + i4) = *(uint2*)hh;
}

// ---------------------------------------------------------------------------
// Wq/Wk/Wv [H][D][HS] -> Wt[m*16+h][s][c] K-major fp16 (smem transpose)
// ---------------------------------------------------------------------------
__global__ __launch_bounds__(256) void conv_wt(
    const float* __restrict__ Wq, const float* __restrict__ Wk, const float* __restrict__ Wv)
{
    __shared__ float tile[32][33];
    int z = blockIdx.z;
    int m = z >> 4, h = z & 15;
    int c0 = blockIdx.x * 32, s0 = blockIdx.y * 32;
    int tx = threadIdx.x, ty = threadIdx.y;
    const float* W = (m == 0) ? Wq : (m == 1) ? Wk : Wv;
    const float* Wh_ = W + (size_t)h * D_ * HS;
#pragma unroll
    for (int i = 0; i < 4; i++) {
        int c = c0 + ty + i * 8;
        tile[ty + i * 8][tx] = Wh_[(size_t)c * HS + s0 + tx];
    }
    __syncthreads();
#pragma unroll
    for (int i = 0; i < 4; i++) {
        int sl = ty + i * 8;
        int row = z * 64 + s0 + sl;
        g_wth[(size_t)row * D_ + c0 + tx] = __float2half_rn(tile[tx][sl]);
    }
}

// ---------------------------------------------------------------------------
// Single-pass fp16 GEMM: C = A·B^T. 3-stage cp.async, one sync per K-chunk.
// MODE 0: QKV scatter (q scaled 0.125). MODE 1: out = C + bias.
// ---------------------------------------------------------------------------
#define STAGE_B 20480   // 2 arrays * 128 rows * 80 B
#define GEMM_SMEM (3 * STAGE_B)
template <int MODE>
__global__ __launch_bounds__(256, 2) void gemm_f16(
    const __half* __restrict__ Ah, const __half* __restrict__ Bh,
    const float* __restrict__ bias, float* __restrict__ out)
{
    extern __shared__ char smc[];
    const uint32_t sb = smem_u32(smc);
    const int tid = threadIdx.x;
    const int wid = tid >> 5, lane = tid & 31;
    const int wm = wid >> 2, wn = wid & 3;
    const int r0 = blockIdx.x * 128;
    const int brow0 = blockIdx.y * 128;

    const int ldrow = tid >> 2, ldseg = tid & 3;
    const uint32_t dst0 = (uint32_t)(ldrow * 80 + ldseg * 16);
    const size_t gao = (size_t)(r0 + ldrow) * D_ + ldseg * 8;
    const size_t gbo = (size_t)(brow0 + ldrow) * D_ + ldseg * 8;

#define LOAD_CHUNK(c, st) do {                                                  \
    uint32_t _b = sb + (st) * STAGE_B;                                          \
    int _kc = (c) * 32;                                                         \
    _Pragma("unroll")                                                           \
    for (int it = 0; it < 2; ++it) {                                            \
        uint32_t d = _b + dst0 + it * (64 * 80);                                \
        cpasync16(d,         Ah + gao + _kc + (size_t)it * 64 * D_);            \
        cpasync16(d + 10240, Bh + gbo + _kc + (size_t)it * 64 * D_);            \
    }                                                                           \
    asm volatile("cp.async.commit_group;" ::: "memory");                        \
} while (0)

    float acc[4][4][4] = {};
    const uint32_t lmA = (uint32_t)((wm * 64 + (lane & 15)) * 80 + (lane >> 4) * 16);
    const uint32_t lmB = (uint32_t)((wn * 32 + (lane & 15)) * 80 + (lane >> 4) * 16);

    LOAD_CHUNK(0, 0);
    LOAD_CHUNK(1, 1);

    for (int c = 0; c < 32; ++c) {
        asm volatile("cp.async.wait_group 1;" ::: "memory");
        __syncthreads();
        // buffer (c+2)%3 == (c-1)%3: all warps finished compute c-1 (sync above)
        if (c + 2 < 32) LOAD_CHUNK(c + 2, (c + 2) % 3);
        else asm volatile("cp.async.commit_group;" ::: "memory");
        uint32_t base = sb + (c % 3) * STAGE_B;
#pragma unroll
        for (int kk = 0; kk < 2; ++kk) {
            uint32_t ko = (uint32_t)(kk * 32);
            uint32_t ah[4][4], bh[2][4];
#pragma unroll
            for (int mt = 0; mt < 4; ++mt)
                ldmx4(ah[mt], base + lmA + mt * (16 * 80) + ko);
#pragma unroll
            for (int g = 0; g < 2; ++g)
                ldmx4(bh[g], base + 10240 + lmB + g * (16 * 80) + ko);
#pragma unroll
            for (int mt = 0; mt < 4; ++mt)
#pragma unroll
                for (int nt = 0; nt < 4; ++nt) {
                    int g = nt >> 1, od = nt & 1;
                    mma16816(acc[mt][nt], ah[mt], bh[g][od], bh[g][2 + od]);
                }
        }
    }

    const int erow = lane >> 2, ecol = (lane & 3) * 2;
#pragma unroll
    for (int mt = 0; mt < 4; ++mt) {
#pragma unroll
        for (int nt = 0; nt < 4; ++nt) {
            int gcol = brow0 + wn * 32 + nt * 8 + ecol;
            int grow = r0 + wm * 64 + mt * 16 + erow;
            if (MODE == 0) {
                int m = gcol >> 10, rem = gcol & 1023;
                int h = rem >> 6, s = rem & 63;
                __half* dsel = (m == 0) ? g_qh : (m == 1) ? g_kh : g_vh;
                float sc = (m == 0) ? 0.125f : 1.0f;
#pragma unroll
                for (int half = 0; half < 2; ++half) {
                    int r = grow + half * 8;
                    int b = r >> 10, t = r & 1023;
                    size_t idx = ((size_t)(b * H_ + h) * T_ + t) * HS + s;
                    *(uint32_t*)(dsel + idx) =
                        pack_h2(acc[mt][nt][half * 2] * sc, acc[mt][nt][half * 2 + 1] * sc);
                }
            } else {
                float2 bv = *(const float2*)(bias + gcol);
#pragma unroll
                for (int half = 0; half < 2; ++half) {
                    int r = grow + half * 8;
                    *(float2*)(out + (size_t)r * D_ + gcol) =
                        make_float2(acc[mt][nt][half * 2] + bv.x,
                                    acc[mt][nt][half * 2 + 1] + bv.y);
                }
            }
        }
    }
#undef LOAD_CHUNK
}

// ---------------------------------------------------------------------------
// Single-pass fp16 tensor-core causal flash attention.
// ---------------------------------------------------------------------------
#define AT_PITCH 144
#define AT_ARR 9216           // 64 rows * 144 B
#define AT_STAGE 18432        // K, V
#define AT_SMEM (2 * AT_STAGE)
__global__ __launch_bounds__(256, 2) void attn_mma()
{
    extern __shared__ char smc[];
    const uint32_t sb = smem_u32(smc);
    const int tid = threadIdx.x, wid = tid >> 5, lane = tid & 31;
    const int qt = 7 - blockIdx.x;
    const int h = blockIdx.y, b = blockIdx.z;
    const int bh = b * H_ + h;
    const size_t bhoff = (size_t)bh * T_ * HS;

    const __half* qp = g_qh + bhoff + (size_t)qt * 128 * HS;
    const __half* kh = g_kh + bhoff;
    const __half* vh = g_vh + bhoff;

    // ---- stage Q, load fragments ----
#pragma unroll
    for (int it = 0; it < 4; ++it) {
        int u = tid + it * 256;
        int row = u >> 3, seg = u & 7;
        *(uint4*)(smc + row * AT_PITCH + seg * 16) =
            *(const uint4*)(qp + row * HS + seg * 8);
    }
    __syncthreads();
    uint32_t aq[4][4];
    {
        uint32_t qa = sb + (uint32_t)((wid * 16 + (lane & 15)) * AT_PITCH + (lane >> 4) * 16);
#pragma unroll
        for (int kk = 0; kk < 4; ++kk)
            ldmx4(aq[kk], qa + kk * 32);
    }
    __syncthreads();

    const int nkt = 2 * qt + 2;
    const int lrow = tid >> 2, lq = tid & 3;

#define LOADKV(kt, st) do {                                                     \
    uint32_t _d = sb + (st) * AT_STAGE + (uint32_t)(lrow * AT_PITCH + lq * 16);  \
    size_t _so = (size_t)((kt) * 64 + lrow) * HS + lq * 8;                      \
    cpasync16(_d,              kh + _so); cpasync16(_d + 64,              kh + _so + 32); \
    cpasync16(_d + AT_ARR,     vh + _so); cpasync16(_d + AT_ARR + 64,     vh + _so + 32); \
    asm volatile("cp.async.commit_group;" ::: "memory");                        \
} while (0)

    float o[8][4] = {};
    float m0 = -INFINITY, m1 = -INFINITY, l0 = 0.f, l1 = 0.f;
    const int r0 = lane >> 2, c0l = (lane & 3) * 2;
    const int qrow0 = qt * 128 + wid * 16 + r0;

    LOADKV(0, 0);
    LOADKV(1, 1);

    for (int kt = 0; kt < nkt; ++kt) {
        asm volatile("cp.async.wait_group 1;" ::: "memory");
        __syncthreads();
        uint32_t kb = sb + (kt & 1) * AT_STAGE;

        // ---- S = q K^T ----
        float sa[8][4] = {};
#pragma unroll
        for (int kk = 0; kk < 4; ++kk) {
#pragma unroll
            for (int g = 0; g < 4; ++g) {
                uint32_t bhf[4];
                ldmx4(bhf, kb + (uint32_t)((g * 16 + (lane & 15)) * AT_PITCH + kk * 32 + (lane >> 4) * 16));
#pragma unroll
                for (int od = 0; od < 2; ++od)
                    mma16816(sa[g * 2 + od], aq[kk], bhf[od], bhf[2 + od]);
            }
        }

        if (kt >= 2 * qt) {
#pragma unroll
            for (int nt = 0; nt < 8; ++nt) {
                int colb = kt * 64 + nt * 8 + c0l;
                if (colb > qrow0)     sa[nt][0] = -INFINITY;
                if (colb + 1 > qrow0) sa[nt][1] = -INFINITY;
                if (colb > qrow0 + 8)     sa[nt][2] = -INFINITY;
                if (colb + 1 > qrow0 + 8) sa[nt][3] = -INFINITY;
            }
        }

        float mx0 = -INFINITY, mx1 = -INFINITY;
#pragma unroll
        for (int nt = 0; nt < 8; ++nt) {
            mx0 = fmaxf(mx0, fmaxf(sa[nt][0], sa[nt][1]));
            mx1 = fmaxf(mx1, fmaxf(sa[nt][2], sa[nt][3]));
        }
        mx0 = fmaxf(mx0, __shfl_xor_sync(0xffffffffu, mx0, 1));
        mx0 = fmaxf(mx0, __shfl_xor_sync(0xffffffffu, mx0, 2));
        mx1 = fmaxf(mx1, __shfl_xor_sync(0xffffffffu, mx1, 1));
        mx1 = fmaxf(mx1, __shfl_xor_sync(0xffffffffu, mx1, 2));
        float mn0 = fmaxf(m0, mx0), mn1 = fmaxf(m1, mx1);
        float cr0 = __expf(m0 - mn0), cr1 = __expf(m1 - mn1);
        m0 = mn0; m1 = mn1;
        float ls0 = 0.f, ls1 = 0.f;
#pragma unroll
        for (int nt = 0; nt < 8; ++nt) {
            sa[nt][0] = __expf(sa[nt][0] - mn0); ls0 += sa[nt][0];
            sa[nt][1] = __expf(sa[nt][1] - mn0); ls0 += sa[nt][1];
            sa[nt][2] = __expf(sa[nt][2] - mn1); ls1 += sa[nt][2];
            sa[nt][3] = __expf(sa[nt][3] - mn1); ls1 += sa[nt][3];
        }
        ls0 += __shfl_xor_sync(0xffffffffu, ls0, 1);
        ls0 += __shfl_xor_sync(0xffffffffu, ls0, 2);
        ls1 += __shfl_xor_sync(0xffffffffu, ls1, 1);
        ls1 += __shfl_xor_sync(0xffffffffu, ls1, 2);
        l0 = l0 * cr0 + ls0;
        l1 = l1 * cr1 + ls1;
#pragma unroll
        for (int nt = 0; nt < 8; ++nt) {
            o[nt][0] *= cr0; o[nt][1] *= cr0;
            o[nt][2] *= cr1; o[nt][3] *= cr1;
        }

        // ---- O += P V ----
#pragma unroll
        for (int kk = 0; kk < 4; ++kk) {
            uint32_t ph[4];
            ph[0] = pack_h2(sa[2 * kk][0],     sa[2 * kk][1]);
            ph[1] = pack_h2(sa[2 * kk][2],     sa[2 * kk][3]);
            ph[2] = pack_h2(sa[2 * kk + 1][0], sa[2 * kk + 1][1]);
            ph[3] = pack_h2(sa[2 * kk + 1][2], sa[2 * kk + 1][3]);
#pragma unroll
            for (int jj = 0; jj < 4; ++jj) {
                uint32_t vhf[4];
                ldmx4t(vhf, kb + AT_ARR +
                    (uint32_t)((kk * 16 + (lane & 15)) * AT_PITCH + jj * 32 + (lane >> 4) * 16));
                mma16816(o[jj * 2],     ph, vhf[0], vhf[1]);
                mma16816(o[jj * 2 + 1], ph, vhf[2], vhf[3]);
            }
        }
        __syncthreads();
        if (kt + 2 < nkt) LOADKV(kt + 2, kt & 1);
        else asm volatile("cp.async.commit_group;" ::: "memory");
    }

    float inv0 = 1.f / l0, inv1 = 1.f / l1;
#pragma unroll
    for (int nt = 0; nt < 8; ++nt) {
        int col = nt * 8 + c0l;
        size_t i0 = ((size_t)b * T_ + qrow0) * D_ + h * 64 + col;
        size_t i1 = i0 + (size_t)8 * D_;
        *(uint32_t*)(g_yh + i0) = pack_h2(o[nt][0] * inv0, o[nt][1] * inv0);
        *(uint32_t*)(g_yh + i1) = pack_h2(o[nt][2] * inv1, o[nt][3] * inv1);
    }
#undef LOADKV
}

// ---------------------------------------------------------------------------
extern "C" void kernel_launch(void* const* d_in, const int* in_sizes, int n_in,
                              void* d_out, int out_size)
{
    const float* x  = (const float*)d_in[0];
    const float* Wq = (const float*)d_in[1];
    const float* Wk = (const float*)d_in[2];
    const float* Wv = (const float*)d_in[3];
    const float* Wo = (const float*)d_in[4];
    const float* bo = (const float*)d_in[5];
    float* out = (float*)d_out;

    cudaFuncSetAttribute(gemm_f16<0>, cudaFuncAttributeMaxDynamicSharedMemorySize, GEMM_SMEM);
    cudaFuncSetAttribute(gemm_f16<1>, cudaFuncAttributeMaxDynamicSharedMemorySize, GEMM_SMEM);
    cudaFuncSetAttribute(attn_mma, cudaFuncAttributeMaxDynamicSharedMemorySize, AT_SMEM);

    __half *xh, *wth, *yh, *woh;
    cudaGetSymbolAddress((void**)&xh,  g_xh);
    cudaGetSymbolAddress((void**)&wth, g_wth);
    cudaGetSymbolAddress((void**)&yh,  g_yh);
    cudaGetSymbolAddress((void**)&woh, g_woh);

    conv_single<<<4096, 256>>>(x, xh, B_ * T_ * D_);
    conv_wt<<<dim3(D_ / 32, HS / 32, 48), dim3(32, 8)>>>(Wq, Wk, Wv);
    conv_single<<<1024, 256>>>(Wo, woh, D_ * D_);

    // QKV: A = X[4096,1024] fp16, B = Wt[3072,1024] fp16
    gemm_f16<0><<<dim3(32, 24), 256, GEMM_SMEM>>>(xh, wth, bo, out);

    attn_mma<<<dim3(8, H_, B_), 256, AT_SMEM>>>();

    // O-proj: A = Y[4096,1024] fp16, B = Wo[1024,1024] fp16
    gemm_f16<1><<<dim3(32, 8), 256, GEMM_SMEM>>>(yh, woh, bo, out);
}